// round 14
// baseline (speedup 1.0000x reference)
#include <cuda_runtime.h>
#include <cuda_fp16.h>

#define MAXN 100000
#define MAXE 1600000
#define HIDC 64
#define NB 64

// ---------------- device scratch (BSS zeroed; zero-restore discipline) ----------------
__device__ __align__(16) int    g_deg[MAXN];          // re-zeroed by k_scanA
__device__ __align__(16) int    g_off[MAXN + 1];
__device__ __align__(16) int    g_cur[MAXN];
__device__ __align__(16) int    g_srcidx[MAXE];
__device__ __align__(16) int    g_part[128];
__device__ __align__(16) __half2 g_y16a[MAXN * 32];
__device__ __align__(16) __half2 g_y16b[MAXN * 32];
__device__ __align__(16) __half2 g_h16[MAXN * 32];    // z16 (layer1) / h16 (layers 2/3)
__device__ __align__(16) __half2 g_agg16[MAXN * 32];  // fp16 aggregate (mm input)
__device__ __align__(16) float  g_v32[MAXN * HIDC];   // v = x@W1r + b1 (layer1 only)
__device__ __align__(16) float  g_stats[3 * 2 * HIDC]; // stats0/1 zeroed by agg64s, stats2 by head
__device__ float g_sumexp;                             // zeroed by head
__device__ __align__(16) float  g_pool[NB * HIDC];     // zeroed by head
__device__ int   g_bcnt[NB];                           // zeroed by head

// ---------------- per-block dtype detection ----------------
__device__ __forceinline__ int block_is64(const long long* __restrict__ ei, int n, int* s_is64) {
    if (threadIdx.x < 32) {
        long long v = ei[threadIdx.x];
        int bad = (v < 0 || v >= (long long)n) ? 1 : 0;
        bad = __any_sync(0xffffffffu, bad);
        if (threadIdx.x == 0) *s_is64 = bad ? 0 : 1;
    }
    __syncthreads();
    return *s_is64;
}
__device__ __forceinline__ int load_idx2(const void* p, int i, int is64) {
    if (is64) return (int)((const long long*)p)[i];
    return ((const int*)p)[i];
}

// ---------------- 1: hist (+ fused prepool) ----------------
__global__ void k_hist(const void* __restrict__ ei, const float* __restrict__ x,
                       const void* __restrict__ batch, int e, int n) {
    __shared__ float ssum[256];
    __shared__ int hist[64];
    __shared__ int s_is64;
    int is64 = block_is64((const long long*)ei, n, &s_is64);
    int tid = threadIdx.x;
    int i = blockIdx.x * 256 + tid;
    if (i < e) atomicAdd(&g_deg[load_idx2(ei, e + i, is64)], 1);
    if (tid < 64) hist[tid] = 0;
    __syncthreads();
    float loc = 0.f;
    if (i < n) {
        loc = expf(__ldg(&x[i * 6 + 4]));
        atomicAdd(&hist[load_idx2(batch, i, is64)], 1);
    }
    ssum[tid] = loc; __syncthreads();
    for (int d = 128; d > 0; d >>= 1) {
        if (tid < d) ssum[tid] += ssum[tid + d];
        __syncthreads();
    }
    if (tid == 0 && ssum[0] != 0.f) atomicAdd(&g_sumexp, ssum[0]);
    if (tid < 64 && hist[tid]) atomicAdd(&g_bcnt[tid], hist[tid]);
}

// ---------------- 2: scanA (prefix scan + fused l1pre phase) ----------------
// Phase 1: per-block exclusive scan of degrees (as before).
// Phase 2: warp = 32 nodes, lane = 2 channels: z = x@W1l (fp16), v = x@W1r + b1 (fp32).
__global__ void __launch_bounds__(1024)
k_scanA(const float* __restrict__ x,
        const float* __restrict__ W1l, const float* __restrict__ W1r,
        const float* __restrict__ b1,
        __half2* __restrict__ z16, float2* __restrict__ v32, int n) {
    __shared__ int sh[1024];
    __shared__ float sWl[6 * 64];
    __shared__ float sWr[6 * 64];
    __shared__ float sb[64];
    int t = threadIdx.x;
    int i = blockIdx.x * 1024 + t;
    int v = (i < n) ? g_deg[i] : 0;
    sh[t] = v;
    if (t < 384) { sWl[t] = W1l[t]; sWr[t] = W1r[t]; }
    else if (t < 448) sb[t - 384] = b1[t - 384];
    __syncthreads();
    for (int d = 1; d < 1024; d <<= 1) {
        int add = (t >= d) ? sh[t - d] : 0;
        __syncthreads();
        sh[t] += add;
        __syncthreads();
    }
    int excl = sh[t] - v;
    if (i < n) { g_off[i] = excl; g_cur[i] = excl; g_deg[i] = 0; }
    if (t == 1023) g_part[blockIdx.x] = sh[1023];

    // ---- phase 2: l1pre ----
    int warp = t >> 5, lane = t & 31, c0 = lane * 2;
    float wl0[6], wl1[6], wr0[6], wr1[6];
#pragma unroll
    for (int k = 0; k < 6; k++) {
        wl0[k] = sWl[k * 64 + c0]; wl1[k] = sWl[k * 64 + c0 + 1];
        wr0[k] = sWr[k * 64 + c0]; wr1[k] = sWr[k * 64 + c0 + 1];
    }
    float bb0 = sb[c0], bb1 = sb[c0 + 1];
    int base = blockIdx.x * 1024 + warp * 32;
#pragma unroll 4
    for (int j = 0; j < 32; j++) {
        int node = base + j;
        if (node >= n) break;
        const float2* xp = (const float2*)(x + node * 6);
        float2 u0 = __ldg(xp), u1 = __ldg(xp + 1), u2 = __ldg(xp + 2);
        float xk[6] = {u0.x, u0.y, u1.x, u1.y, u2.x, u2.y};
        float z0 = 0.f, z1 = 0.f, v0 = bb0, v1 = bb1;
#pragma unroll
        for (int k = 0; k < 6; k++) {
            z0 += xk[k] * wl0[k];
            z1 += xk[k] * wl1[k];
            v0 += xk[k] * wr0[k];
            v1 += xk[k] * wr1[k];
        }
        z16[node * 32 + lane] = __float22half2_rn(make_float2(z0, z1));
        v32[node * 32 + lane] = make_float2(v0, v1);
    }
}

// ---------------- 3: scatter ----------------
__global__ void k_scatter(const void* __restrict__ ei, int e, int n, int nb) {
    __shared__ int sp[128];
    __shared__ int s_is64;
    int is64 = block_is64((const long long*)ei, n, &s_is64);
    int tid = threadIdx.x;
    if (tid < 128) sp[tid] = (tid < nb) ? g_part[tid] : 0;
    __syncthreads();
    for (int d = 1; d < 128; d <<= 1) {
        int v = 0;
        if (tid < 128 && tid >= d) v = sp[tid - d];
        __syncthreads();
        if (tid < 128) sp[tid] += v;
        __syncthreads();
    }
    int ex = 0;
    if (tid > 0 && tid < 128) ex = sp[tid - 1];
    __syncthreads();
    if (tid < 128) sp[tid] = ex;
    __syncthreads();

    int i = blockIdx.x * 256 + tid;
    if (i < e) {
        int src = load_idx2(ei, i, is64);
        int dst = load_idx2(ei, e + i, is64);
        int pos = atomicAdd(&g_cur[dst], 1) + sp[dst >> 10];
        g_srcidx[pos] = src;
    }
    if (i < n) g_off[i] += sp[i >> 10];
    if (i == 0) g_off[n] = e;
}

// ---------------- 4: l1agg — coalesced z16 gather, + v, stats, y1 fp16 ----------------
__global__ void __launch_bounds__(256)
k_l1agg(const __half2* __restrict__ z16, const float2* __restrict__ v32,
        __half2* __restrict__ yout, float* __restrict__ stats, int n) {
    __shared__ float redS[8][64];
    __shared__ float redQ[8][64];
    int tid = threadIdx.x;
    int warp = tid >> 5, lane = tid & 31, c0 = lane * 2;
    int base = blockIdx.x * 64 + warp * 8;
    float ls0 = 0.f, ls1 = 0.f, lq0 = 0.f, lq1 = 0.f;

#pragma unroll 1
    for (int j = 0; j < 8; j++) {
        int node = base + j;
        if (node >= n) break;
        int s = g_off[node], t = g_off[node + 1];
        float ax = 0.f, ay = 0.f;
        int e = s;
        for (; e + 8 <= t; e += 8) {
            int i0 = __ldg(&g_srcidx[e]);
            int i1 = __ldg(&g_srcidx[e + 1]);
            int i2 = __ldg(&g_srcidx[e + 2]);
            int i3 = __ldg(&g_srcidx[e + 3]);
            int i4 = __ldg(&g_srcidx[e + 4]);
            int i5 = __ldg(&g_srcidx[e + 5]);
            int i6 = __ldg(&g_srcidx[e + 6]);
            int i7 = __ldg(&g_srcidx[e + 7]);
            float2 f0 = __half22float2(__ldg(&z16[i0 * 32 + lane]));
            float2 f1 = __half22float2(__ldg(&z16[i1 * 32 + lane]));
            float2 f2 = __half22float2(__ldg(&z16[i2 * 32 + lane]));
            float2 f3 = __half22float2(__ldg(&z16[i3 * 32 + lane]));
            float2 f4 = __half22float2(__ldg(&z16[i4 * 32 + lane]));
            float2 f5 = __half22float2(__ldg(&z16[i5 * 32 + lane]));
            float2 f6 = __half22float2(__ldg(&z16[i6 * 32 + lane]));
            float2 f7 = __half22float2(__ldg(&z16[i7 * 32 + lane]));
            ax += ((f0.x + f1.x) + (f2.x + f3.x)) + ((f4.x + f5.x) + (f6.x + f7.x));
            ay += ((f0.y + f1.y) + (f2.y + f3.y)) + ((f4.y + f5.y) + (f6.y + f7.y));
        }
        for (; e < t; e++) {
            int i0 = __ldg(&g_srcidx[e]);
            float2 f = __half22float2(__ldg(&z16[i0 * 32 + lane]));
            ax += f.x; ay += f.y;
        }
        float inv = 1.f / fmaxf((float)(t - s), 1.f);
        float2 v = __ldg(&v32[node * 32 + lane]);
        float y0 = fmaf(ax, inv, v.x);
        float y1 = fmaf(ay, inv, v.y);
        yout[node * 32 + lane] = __float22half2_rn(make_float2(y0, y1));
        ls0 += y0; lq0 += y0 * y0;
        ls1 += y1; lq1 += y1 * y1;
    }
    redS[warp][c0] = ls0; redS[warp][c0 + 1] = ls1;
    redQ[warp][c0] = lq0; redQ[warp][c0 + 1] = lq1;
    __syncthreads();
    if (tid < 64) {
        float s = 0.f, q = 0.f;
#pragma unroll
        for (int w2 = 0; w2 < 8; w2++) { s += redS[w2][tid]; q += redQ[w2][tid]; }
        atomicAdd(&stats[tid], s);
        atomicAdd(&stats[64 + tid], q);
    }
}

// ---------------- 5/8: bnh — h16 = ReLU(BN(y16)) ----------------
__global__ void k_bnh(const __half2* __restrict__ yin, const float* __restrict__ stats,
                      const float* __restrict__ gam, const float* __restrict__ bet,
                      float invn, __half2* __restrict__ h16, int n32) {
    __shared__ float2 sp[64];
    int tid = threadIdx.x;
    if (tid < 64) {
        float mu = stats[tid] * invn;
        float var = stats[64 + tid] * invn - mu * mu;
        float rstd = rsqrtf(var + 1e-5f);
        float sc = rstd * gam[tid];
        sp[tid] = make_float2(sc, bet[tid] - mu * sc);
    }
    __syncthreads();
    int i = blockIdx.x * 256 + tid;
    if (i >= n32) return;
    int c2 = (i & 31) * 2;
    float2 p0 = sp[c2], p1 = sp[c2 + 1];
    float2 f = __half22float2(yin[i]);
    float vx = fmaxf(fmaf(f.x, p0.x, p0.y), 0.f);
    float vy = fmaxf(fmaf(f.y, p1.x, p1.y), 0.f);
    h16[i] = __float22half2_rn(make_float2(vx, vy));
}

// ---------------- 6/9: agg64s — coalesced fp16 gather-mean, fp16 out ----------------
__global__ void k_agg64s(const __half2* __restrict__ h,
                         __half2* __restrict__ aggout, float* __restrict__ zstats, int n) {
    if (blockIdx.x == 0 && threadIdx.x < 128 && zstats) zstats[threadIdx.x] = 0.f;
    int w = (blockIdx.x * blockDim.x + threadIdx.x) >> 5;
    int lane = threadIdx.x & 31;
    if (w >= n) return;
    int s = g_off[w], t = g_off[w + 1];
    float ax = 0.f, ay = 0.f;
    int e = s;
    for (; e + 8 <= t; e += 8) {
        int i0 = __ldg(&g_srcidx[e]);
        int i1 = __ldg(&g_srcidx[e + 1]);
        int i2 = __ldg(&g_srcidx[e + 2]);
        int i3 = __ldg(&g_srcidx[e + 3]);
        int i4 = __ldg(&g_srcidx[e + 4]);
        int i5 = __ldg(&g_srcidx[e + 5]);
        int i6 = __ldg(&g_srcidx[e + 6]);
        int i7 = __ldg(&g_srcidx[e + 7]);
        float2 f0 = __half22float2(__ldg(&h[i0 * 32 + lane]));
        float2 f1 = __half22float2(__ldg(&h[i1 * 32 + lane]));
        float2 f2 = __half22float2(__ldg(&h[i2 * 32 + lane]));
        float2 f3 = __half22float2(__ldg(&h[i3 * 32 + lane]));
        float2 f4 = __half22float2(__ldg(&h[i4 * 32 + lane]));
        float2 f5 = __half22float2(__ldg(&h[i5 * 32 + lane]));
        float2 f6 = __half22float2(__ldg(&h[i6 * 32 + lane]));
        float2 f7 = __half22float2(__ldg(&h[i7 * 32 + lane]));
        ax += ((f0.x + f1.x) + (f2.x + f3.x)) + ((f4.x + f5.x) + (f6.x + f7.x));
        ay += ((f0.y + f1.y) + (f2.y + f3.y)) + ((f4.y + f5.y) + (f6.y + f7.y));
    }
    for (; e < t; e++) {
        int i0 = __ldg(&g_srcidx[e]);
        float2 f = __half22float2(__ldg(&h[i0 * 32 + lane]));
        ax += f.x; ay += f.y;
    }
    float inv = 1.f / fmaxf((float)(t - s), 1.f);
    aggout[w * 32 + lane] = __float22half2_rn(make_float2(ax * inv, ay * inv));
}

// ---------------- 7/10: dense matmul via HMMA + BN-stats ----------------
__global__ void __launch_bounds__(256)
k_mm(const __half2* __restrict__ aggin, const __half2* __restrict__ hin,
     const float* __restrict__ Wl, const float* __restrict__ Wr,
     const float* __restrict__ bias, __half2* __restrict__ yout,
     float* __restrict__ stats, int n) {
    __shared__ unsigned int sW[64 * 65];
    __shared__ float sb[64];
    __shared__ float redS[8][64];
    __shared__ float redQ[8][64];
    int tid = threadIdx.x;
    for (int i = tid; i < 64 * 64; i += 256) {
        int kp = i >> 6, c = i & 63;
        int k0 = kp * 2, k1 = k0 + 1;
        float w0 = (k0 < 64) ? Wl[k0 * 64 + c] : Wr[(k0 - 64) * 64 + c];
        float w1 = (k1 < 64) ? Wl[k1 * 64 + c] : Wr[(k1 - 64) * 64 + c];
        __half2 hw = __floats2half2_rn(w0, w1);
        sW[kp * 65 + c] = *(unsigned int*)&hw;
    }
    if (tid < 64) sb[tid] = bias[tid];
    __syncthreads();

    int warp = tid >> 5, lane = tid & 31;
    int g = lane >> 2, tig = lane & 3;
    int nb = blockIdx.x * 128 + warp * 16;

    float acc[8][4];
#pragma unroll
    for (int nt = 0; nt < 8; nt++) {
        acc[nt][0] = 0.f; acc[nt][1] = 0.f; acc[nt][2] = 0.f; acc[nt][3] = 0.f;
    }

    int row0 = nb + g, row1 = nb + g + 8;
    bool v0 = row0 < n, v1 = row1 < n;
    int r0 = v0 ? row0 : n - 1;
    int r1 = v1 ? row1 : n - 1;

#pragma unroll
    for (int kt = 0; kt < 8; kt++) {
        const __half2* act = (kt < 4) ? aggin : hin;
        int kp = (kt & 3) * 8 + tig;
        unsigned int a0 = *(const unsigned int*)&act[r0 * 32 + kp];
        unsigned int a1 = *(const unsigned int*)&act[r1 * 32 + kp];
        unsigned int a2 = *(const unsigned int*)&act[r0 * 32 + kp + 4];
        unsigned int a3 = *(const unsigned int*)&act[r1 * 32 + kp + 4];
        int kb0 = (kt * 8 + tig) * 65;
        int kb1 = (kt * 8 + tig + 4) * 65;
#pragma unroll
        for (int nt = 0; nt < 8; nt++) {
            unsigned int b0 = sW[kb0 + nt * 8 + g];
            unsigned int b1 = sW[kb1 + nt * 8 + g];
            asm volatile(
                "mma.sync.aligned.m16n8k16.row.col.f32.f16.f16.f32 "
                "{%0,%1,%2,%3}, {%4,%5,%6,%7}, {%8,%9}, {%0,%1,%2,%3};"
                : "+f"(acc[nt][0]), "+f"(acc[nt][1]), "+f"(acc[nt][2]), "+f"(acc[nt][3])
                : "r"(a0), "r"(a1), "r"(a2), "r"(a3), "r"(b0), "r"(b1));
        }
    }

    float s0[8], s1[8], q0[8], q1[8];
#pragma unroll
    for (int nt = 0; nt < 8; nt++) {
        int c0 = nt * 8 + tig * 2;
        float y00 = acc[nt][0] + sb[c0];
        float y01 = acc[nt][1] + sb[c0 + 1];
        float y10 = acc[nt][2] + sb[c0];
        float y11 = acc[nt][3] + sb[c0 + 1];
        if (v0) yout[row0 * 32 + nt * 4 + tig] = __float22half2_rn(make_float2(y00, y01));
        if (v1) yout[row1 * 32 + nt * 4 + tig] = __float22half2_rn(make_float2(y10, y11));
        s0[nt] = (v0 ? y00 : 0.f) + (v1 ? y10 : 0.f);
        s1[nt] = (v0 ? y01 : 0.f) + (v1 ? y11 : 0.f);
        q0[nt] = (v0 ? y00 * y00 : 0.f) + (v1 ? y10 * y10 : 0.f);
        q1[nt] = (v0 ? y01 * y01 : 0.f) + (v1 ? y11 * y11 : 0.f);
    }
#pragma unroll
    for (int d = 4; d <= 16; d <<= 1) {
#pragma unroll
        for (int nt = 0; nt < 8; nt++) {
            s0[nt] += __shfl_xor_sync(0xffffffffu, s0[nt], d);
            s1[nt] += __shfl_xor_sync(0xffffffffu, s1[nt], d);
            q0[nt] += __shfl_xor_sync(0xffffffffu, q0[nt], d);
            q1[nt] += __shfl_xor_sync(0xffffffffu, q1[nt], d);
        }
    }
    if (g == 0) {
#pragma unroll
        for (int nt = 0; nt < 8; nt++) {
            int c0 = nt * 8 + tig * 2;
            redS[warp][c0] = s0[nt]; redS[warp][c0 + 1] = s1[nt];
            redQ[warp][c0] = q0[nt]; redQ[warp][c0 + 1] = q1[nt];
        }
    }
    __syncthreads();
    if (tid < 64) {
        float s = 0.f, q = 0.f;
#pragma unroll
        for (int w2 = 0; w2 < 8; w2++) { s += redS[w2][tid]; q += redQ[w2][tid]; }
        atomicAdd(&stats[tid], s);
        atomicAdd(&stats[64 + tid], q);
    }
}

// ---------------- 11: pooling (BN3 + ReLU on read) ----------------
__global__ void k_pool(const void* __restrict__ batch, const void* __restrict__ ei,
                       const float* __restrict__ x,
                       const __half2* __restrict__ y16,
                       const float* __restrict__ stats,
                       const float* __restrict__ gam, const float* __restrict__ bet,
                       float invn, int n) {
    __shared__ float w[64];
    __shared__ int bb[64];
    __shared__ float2 sscsh[64];
    __shared__ int s_is64;
    int is64 = block_is64((const long long*)ei, n, &s_is64);
    int tid = threadIdx.x;  // 0..31
    int base = blockIdx.x * 64;
    float S = g_sumexp;
    for (int j = tid; j < 64; j += 32) {
        int i = base + j;
        if (i < n) { w[j] = expf(__ldg(&x[i * 6 + 4])) / S; bb[j] = load_idx2(batch, i, is64); }
        else { w[j] = 0.f; bb[j] = -1; }
        float mu = stats[j] * invn;
        float var = stats[64 + j] * invn - mu * mu;
        float rstd = rsqrtf(var + 1e-5f);
        float sc = rstd * gam[j];
        sscsh[j] = make_float2(sc, bet[j] - mu * sc);
    }
    __syncthreads();
    int c0 = tid * 2;
    float2 p0 = sscsh[c0], p1 = sscsh[c0 + 1];
    int m = n - base; if (m > 64) m = 64;
#define BNV(f) make_float2(fmaxf(fmaf((f).x, p0.x, p0.y), 0.f), fmaxf(fmaf((f).y, p1.x, p1.y), 0.f))
    if (m == 64 && bb[0] == bb[63]) {
        float ax0 = 0.f, ay0 = 0.f, ax1 = 0.f, ay1 = 0.f;
        float ax2 = 0.f, ay2 = 0.f, ax3 = 0.f, ay3 = 0.f;
        for (int j = 0; j < 64; j += 4) {
            float2 f0 = BNV(__half22float2(__ldg(&y16[(base + j + 0) * 32 + tid])));
            float2 f1 = BNV(__half22float2(__ldg(&y16[(base + j + 1) * 32 + tid])));
            float2 f2 = BNV(__half22float2(__ldg(&y16[(base + j + 2) * 32 + tid])));
            float2 f3 = BNV(__half22float2(__ldg(&y16[(base + j + 3) * 32 + tid])));
            ax0 += w[j] * f0.x;     ay0 += w[j] * f0.y;
            ax1 += w[j + 1] * f1.x; ay1 += w[j + 1] * f1.y;
            ax2 += w[j + 2] * f2.x; ay2 += w[j + 2] * f2.y;
            ax3 += w[j + 3] * f3.x; ay3 += w[j + 3] * f3.y;
        }
        atomicAdd(&g_pool[bb[0] * 64 + c0],     (ax0 + ax1) + (ax2 + ax3));
        atomicAdd(&g_pool[bb[0] * 64 + c0 + 1], (ay0 + ay1) + (ay2 + ay3));
    } else {
        float accx = 0.f, accy = 0.f;
        int cur = bb[0];
        for (int j = 0; j < m; j++) {
            int b = bb[j];
            if (b != cur) {
                if (cur >= 0) {
                    atomicAdd(&g_pool[cur * 64 + c0], accx);
                    atomicAdd(&g_pool[cur * 64 + c0 + 1], accy);
                }
                accx = 0.f; accy = 0.f; cur = b;
            }
            float2 f = BNV(__half22float2(__ldg(&y16[(base + j) * 32 + tid])));
            accx += w[j] * f.x; accy += w[j] * f.y;
        }
        if (cur >= 0 && m > 0) {
            atomicAdd(&g_pool[cur * 64 + c0], accx);
            atomicAdd(&g_pool[cur * 64 + c0 + 1], accy);
        }
    }
#undef BNV
}

// ---------------- 12: heads (+ restore zeros) ----------------
__global__ void k_head(const float* __restrict__ phW1, const float* __restrict__ phb1,
                       const float* __restrict__ phW2, const float* __restrict__ phb2,
                       const float* __restrict__ trW1, const float* __restrict__ trb1,
                       const float* __restrict__ trW2, const float* __restrict__ trb2,
                       float* __restrict__ zstats, float* __restrict__ out) {
    __shared__ float pool[64 * 64];
    __shared__ float hid[64 * 32];
    __shared__ float hidt[64 * 16];
    int tid = threadIdx.x;
    for (int i = tid; i < 64 * 64; i += 256) {
        int b = i >> 6;
        float c = (float)g_bcnt[b];
        pool[i] = g_pool[i] / fmaxf(c, 1.f);
    }
    __syncthreads();
    for (int i = tid; i < 64 * 64; i += 256) g_pool[i] = 0.f;
    if (tid < 64) g_bcnt[tid] = 0;
    if (tid < 128) zstats[tid] = 0.f;
    if (tid == 0) g_sumexp = 0.f;

    for (int i = tid; i < 64 * 32; i += 256) {
        int b = i >> 5, j = i & 31;
        float s = phb1[j];
        for (int k = 0; k < 64; k++) s += pool[b * 64 + k] * phW1[k * 32 + j];
        hid[i] = fmaxf(s, 0.f);
    }
    for (int i = tid; i < 64 * 16; i += 256) {
        int b = i >> 4, j = i & 15;
        float s = trb1[j];
        for (int k = 0; k < 64; k++) s += pool[b * 64 + k] * trW1[k * 16 + j];
        hidt[i] = fmaxf(s, 0.f);
    }
    __syncthreads();
    for (int i = tid; i < 64 * 3; i += 256) {
        int b = i / 3, j = i - b * 3;
        float s = phb2[j];
        for (int k = 0; k < 32; k++) s += hid[b * 32 + k] * phW2[k * 3 + j];
        out[i] = s;
    }
    for (int i = tid; i < 64; i += 256) {
        float s = trb2[0];
        for (int k = 0; k < 16; k++) s += hidt[i * 16 + k] * trW2[k];
        out[192 + i] = 1.f / (1.f + expf(-s));
    }
}

// ---------------- launch ----------------
extern "C" void kernel_launch(void* const* d_in, const int* in_sizes, int n_in,
                              void* d_out, int out_size) {
    const float* x   = (const float*)d_in[0];
    const void*  ei  = d_in[1];
    const void*  bat = d_in[2];
    const float* W1l = (const float*)d_in[3];
    const float* b1  = (const float*)d_in[4];
    const float* W1r = (const float*)d_in[5];
    const float* W2l = (const float*)d_in[6];
    const float* b2  = (const float*)d_in[7];
    const float* W2r = (const float*)d_in[8];
    const float* W3l = (const float*)d_in[9];
    const float* b3  = (const float*)d_in[10];
    const float* W3r = (const float*)d_in[11];
    const float* g1  = (const float*)d_in[12];
    const float* be1 = (const float*)d_in[13];
    const float* g2  = (const float*)d_in[14];
    const float* be2 = (const float*)d_in[15];
    const float* g3  = (const float*)d_in[16];
    const float* be3 = (const float*)d_in[17];
    const float* phW1 = (const float*)d_in[18];
    const float* phb1 = (const float*)d_in[19];
    const float* phW2 = (const float*)d_in[20];
    const float* phb2 = (const float*)d_in[21];
    const float* trW1 = (const float*)d_in[22];
    const float* trb1 = (const float*)d_in[23];
    const float* trW2 = (const float*)d_in[24];
    const float* trb2 = (const float*)d_in[25];
    float* out = (float*)d_out;

    int n = in_sizes[0] / 6;
    int e = in_sizes[1] / 2;

    float *p_v32, *p_stats;
    __half2 *p_ya, *p_yb, *p_h16, *p_agg16;
    cudaGetSymbolAddress((void**)&p_v32, g_v32);
    cudaGetSymbolAddress((void**)&p_stats, g_stats);
    cudaGetSymbolAddress((void**)&p_ya, g_y16a);
    cudaGetSymbolAddress((void**)&p_yb, g_y16b);
    cudaGetSymbolAddress((void**)&p_h16, g_h16);
    cudaGetSymbolAddress((void**)&p_agg16, g_agg16);

    int nb = (n + 1023) / 1024;
    int eBlocks = (e + 255) / 256;
    int aggBlocks = (n * 32 + 255) / 256;   // warp-per-node grids
    int mmBlocks = (n + 63) / 64;           // warp-per-8-nodes grids
    int mmaBlocks = (n + 127) / 128;        // HMMA: 128 nodes per block
    int bnBlocks = (n * 32 + 255) / 256;
    float invn = 1.f / (float)n;

    // 1-3: CSR (+ l1pre fused into scanA)
    k_hist<<<eBlocks, 256>>>(ei, x, bat, e, n);
    k_scanA<<<nb, 1024>>>(x, W1l, W1r, b1, p_h16, (float2*)p_v32, n);
    k_scatter<<<eBlocks, 256>>>(ei, e, n, nb);

    // 4: layer 1 gather (linearity)
    k_l1agg<<<mmBlocks, 256>>>(p_h16, (const float2*)p_v32, p_ya, p_stats + 0 * 128, n);

    // 5-7: layer 2 (fp16 datapath, HMMA matmul)
    k_bnh<<<bnBlocks, 256>>>(p_ya, p_stats + 0 * 128, g1, be1, invn, p_h16, n * 32);
    k_agg64s<<<aggBlocks, 256>>>(p_h16, p_agg16, p_stats + 0 * 128, n);
    k_mm<<<mmaBlocks, 256>>>(p_agg16, p_h16, W2l, W2r, b2, p_yb, p_stats + 1 * 128, n);

    // 8-10: layer 3
    k_bnh<<<bnBlocks, 256>>>(p_yb, p_stats + 1 * 128, g2, be2, invn, p_h16, n * 32);
    k_agg64s<<<aggBlocks, 256>>>(p_h16, p_agg16, p_stats + 1 * 128, n);
    k_mm<<<mmaBlocks, 256>>>(p_agg16, p_h16, W3l, W3r, b3, p_ya, p_stats + 2 * 128, n);

    // 11-12: pooling + heads
    k_pool<<<mmBlocks, 32>>>(bat, ei, x, p_ya, p_stats + 2 * 128, g3, be3, invn, n);
    k_head<<<1, 256>>>(phW1, phb1, phW2, phb2, trW1, trb1, trW2, trb2, p_stats + 2 * 128, out);
}

// round 15
// speedup vs baseline: 1.0207x; 1.0207x over previous
#include <cuda_runtime.h>
#include <cuda_fp16.h>

#define MAXN 100000
#define MAXE 1600000
#define HIDC 64
#define NB 64

// ---------------- device scratch (BSS zeroed; zero-restore discipline) ----------------
__device__ __align__(16) int    g_deg[MAXN];          // re-zeroed by k_scanA
__device__ __align__(16) int    g_off[MAXN + 1];
__device__ __align__(16) int    g_cur[MAXN];
__device__ __align__(16) int    g_srcidx[MAXE];
__device__ __align__(16) int    g_part[128];
__device__ __align__(16) __half2 g_y16a[MAXN * 32];
__device__ __align__(16) __half2 g_y16b[MAXN * 32];
__device__ __align__(16) __half2 g_h16[MAXN * 32];    // z16 (layer1) / h16 (layers 2/3)
__device__ __align__(16) __half2 g_agg16[MAXN * 32];  // fp16 aggregate (mm input)
__device__ __align__(16) float  g_v32[MAXN * HIDC];   // v = x@W1r + b1 (layer1 only)
__device__ __align__(16) float  g_stats[3 * 2 * HIDC]; // stats0/1 zeroed by agg64s, stats2 by head
__device__ float g_sumexp;                             // zeroed by head
__device__ __align__(16) float  g_pool[NB * HIDC];     // zeroed by head
__device__ int   g_bcnt[NB];                           // zeroed by head

// ---------------- per-block dtype detection ----------------
__device__ __forceinline__ int block_is64(const long long* __restrict__ ei, int n, int* s_is64) {
    if (threadIdx.x < 32) {
        long long v = ei[threadIdx.x];
        int bad = (v < 0 || v >= (long long)n) ? 1 : 0;
        bad = __any_sync(0xffffffffu, bad);
        if (threadIdx.x == 0) *s_is64 = bad ? 0 : 1;
    }
    __syncthreads();
    return *s_is64;
}
__device__ __forceinline__ int load_idx2(const void* p, int i, int is64) {
    if (is64) return (int)((const long long*)p)[i];
    return ((const int*)p)[i];
}

// ---------------- 1: hist (+ fused prepool) ----------------
__global__ void k_hist(const void* __restrict__ ei, const float* __restrict__ x,
                       const void* __restrict__ batch, int e, int n) {
    __shared__ float ssum[256];
    __shared__ int hist[64];
    __shared__ int s_is64;
    int is64 = block_is64((const long long*)ei, n, &s_is64);
    int tid = threadIdx.x;
    int i = blockIdx.x * 256 + tid;
    if (i < e) atomicAdd(&g_deg[load_idx2(ei, e + i, is64)], 1);
    if (tid < 64) hist[tid] = 0;
    __syncthreads();
    float loc = 0.f;
    if (i < n) {
        loc = expf(__ldg(&x[i * 6 + 4]));
        atomicAdd(&hist[load_idx2(batch, i, is64)], 1);
    }
    ssum[tid] = loc; __syncthreads();
    for (int d = 128; d > 0; d >>= 1) {
        if (tid < d) ssum[tid] += ssum[tid + d];
        __syncthreads();
    }
    if (tid == 0 && ssum[0] != 0.f) atomicAdd(&g_sumexp, ssum[0]);
    if (tid < 64 && hist[tid]) atomicAdd(&g_bcnt[tid], hist[tid]);
}

// ---------------- 2: scanA (prefix scan + fused l1pre phase) ----------------
__global__ void __launch_bounds__(1024)
k_scanA(const float* __restrict__ x,
        const float* __restrict__ W1l, const float* __restrict__ W1r,
        const float* __restrict__ b1,
        __half2* __restrict__ z16, float2* __restrict__ v32, int n) {
    __shared__ int sh[1024];
    __shared__ float sWl[6 * 64];
    __shared__ float sWr[6 * 64];
    __shared__ float sb[64];
    int t = threadIdx.x;
    int i = blockIdx.x * 1024 + t;
    int v = (i < n) ? g_deg[i] : 0;
    sh[t] = v;
    if (t < 384) { sWl[t] = W1l[t]; sWr[t] = W1r[t]; }
    else if (t < 448) sb[t - 384] = b1[t - 384];
    __syncthreads();
    for (int d = 1; d < 1024; d <<= 1) {
        int add = (t >= d) ? sh[t - d] : 0;
        __syncthreads();
        sh[t] += add;
        __syncthreads();
    }
    int excl = sh[t] - v;
    if (i < n) { g_off[i] = excl; g_cur[i] = excl; g_deg[i] = 0; }
    if (t == 1023) g_part[blockIdx.x] = sh[1023];

    // ---- phase 2: l1pre ----
    int warp = t >> 5, lane = t & 31, c0 = lane * 2;
    float wl0[6], wl1[6], wr0[6], wr1[6];
#pragma unroll
    for (int k = 0; k < 6; k++) {
        wl0[k] = sWl[k * 64 + c0]; wl1[k] = sWl[k * 64 + c0 + 1];
        wr0[k] = sWr[k * 64 + c0]; wr1[k] = sWr[k * 64 + c0 + 1];
    }
    float bb0 = sb[c0], bb1 = sb[c0 + 1];
    int base = blockIdx.x * 1024 + warp * 32;
#pragma unroll 4
    for (int j = 0; j < 32; j++) {
        int node = base + j;
        if (node >= n) break;
        const float2* xp = (const float2*)(x + node * 6);
        float2 u0 = __ldg(xp), u1 = __ldg(xp + 1), u2 = __ldg(xp + 2);
        float xk[6] = {u0.x, u0.y, u1.x, u1.y, u2.x, u2.y};
        float z0 = 0.f, z1 = 0.f, v0 = bb0, v1 = bb1;
#pragma unroll
        for (int k = 0; k < 6; k++) {
            z0 += xk[k] * wl0[k];
            z1 += xk[k] * wl1[k];
            v0 += xk[k] * wr0[k];
            v1 += xk[k] * wr1[k];
        }
        z16[node * 32 + lane] = __float22half2_rn(make_float2(z0, z1));
        v32[node * 32 + lane] = make_float2(v0, v1);
    }
}

// ---------------- 3: scatter ----------------
__global__ void k_scatter(const void* __restrict__ ei, int e, int n, int nb) {
    __shared__ int sp[128];
    __shared__ int s_is64;
    int is64 = block_is64((const long long*)ei, n, &s_is64);
    int tid = threadIdx.x;
    if (tid < 128) sp[tid] = (tid < nb) ? g_part[tid] : 0;
    __syncthreads();
    for (int d = 1; d < 128; d <<= 1) {
        int v = 0;
        if (tid < 128 && tid >= d) v = sp[tid - d];
        __syncthreads();
        if (tid < 128) sp[tid] += v;
        __syncthreads();
    }
    int ex = 0;
    if (tid > 0 && tid < 128) ex = sp[tid - 1];
    __syncthreads();
    if (tid < 128) sp[tid] = ex;
    __syncthreads();

    int i = blockIdx.x * 256 + tid;
    if (i < e) {
        int src = load_idx2(ei, i, is64);
        int dst = load_idx2(ei, e + i, is64);
        int pos = atomicAdd(&g_cur[dst], 1) + sp[dst >> 10];
        g_srcidx[pos] = src;
    }
    if (i < n) g_off[i] += sp[i >> 10];
    if (i == 0) g_off[n] = e;
}

// ---------------- gather macro: MLP-16 chunk, then MLP-8, then scalar ----------------
#define GATHER_MEAN(SRC, ax, ay, s_, t_, lane_)                                        \
    {                                                                                  \
        int e_ = s_;                                                                   \
        for (; e_ + 16 <= t_; e_ += 16) {                                              \
            int idx_[16];                                                              \
            _Pragma("unroll")                                                          \
            for (int u_ = 0; u_ < 16; u_++) idx_[u_] = __ldg(&g_srcidx[e_ + u_]);      \
            _Pragma("unroll")                                                          \
            for (int u_ = 0; u_ < 16; u_++) {                                          \
                float2 f_ = __half22float2(__ldg(&(SRC)[idx_[u_] * 32 + lane_]));      \
                ax += f_.x; ay += f_.y;                                                \
            }                                                                          \
        }                                                                              \
        for (; e_ + 8 <= t_; e_ += 8) {                                                \
            int idx_[8];                                                               \
            _Pragma("unroll")                                                          \
            for (int u_ = 0; u_ < 8; u_++) idx_[u_] = __ldg(&g_srcidx[e_ + u_]);       \
            _Pragma("unroll")                                                          \
            for (int u_ = 0; u_ < 8; u_++) {                                           \
                float2 f_ = __half22float2(__ldg(&(SRC)[idx_[u_] * 32 + lane_]));      \
                ax += f_.x; ay += f_.y;                                                \
            }                                                                          \
        }                                                                              \
        for (; e_ < t_; e_++) {                                                        \
            int i0_ = __ldg(&g_srcidx[e_]);                                            \
            float2 f_ = __half22float2(__ldg(&(SRC)[i0_ * 32 + lane_]));               \
            ax += f_.x; ay += f_.y;                                                    \
        }                                                                              \
    }

// ---------------- 4: l1agg — MLP-16 z16 gather, + v, stats, y1 fp16 ----------------
__global__ void __launch_bounds__(256)
k_l1agg(const __half2* __restrict__ z16, const float2* __restrict__ v32,
        __half2* __restrict__ yout, float* __restrict__ stats, int n) {
    __shared__ float redS[8][64];
    __shared__ float redQ[8][64];
    int tid = threadIdx.x;
    int warp = tid >> 5, lane = tid & 31, c0 = lane * 2;
    int base = blockIdx.x * 64 + warp * 8;
    float ls0 = 0.f, ls1 = 0.f, lq0 = 0.f, lq1 = 0.f;

#pragma unroll 1
    for (int j = 0; j < 8; j++) {
        int node = base + j;
        if (node >= n) break;
        int s = g_off[node], t = g_off[node + 1];
        float ax = 0.f, ay = 0.f;
        GATHER_MEAN(z16, ax, ay, s, t, lane)
        float inv = 1.f / fmaxf((float)(t - s), 1.f);
        float2 v = __ldg(&v32[node * 32 + lane]);
        float y0 = fmaf(ax, inv, v.x);
        float y1 = fmaf(ay, inv, v.y);
        yout[node * 32 + lane] = __float22half2_rn(make_float2(y0, y1));
        ls0 += y0; lq0 += y0 * y0;
        ls1 += y1; lq1 += y1 * y1;
    }
    redS[warp][c0] = ls0; redS[warp][c0 + 1] = ls1;
    redQ[warp][c0] = lq0; redQ[warp][c0 + 1] = lq1;
    __syncthreads();
    if (tid < 64) {
        float s = 0.f, q = 0.f;
#pragma unroll
        for (int w2 = 0; w2 < 8; w2++) { s += redS[w2][tid]; q += redQ[w2][tid]; }
        atomicAdd(&stats[tid], s);
        atomicAdd(&stats[64 + tid], q);
    }
}

// ---------------- 5/8: bnh — h16 = ReLU(BN(y16)) ----------------
__global__ void k_bnh(const __half2* __restrict__ yin, const float* __restrict__ stats,
                      const float* __restrict__ gam, const float* __restrict__ bet,
                      float invn, __half2* __restrict__ h16, int n32) {
    __shared__ float2 sp[64];
    int tid = threadIdx.x;
    if (tid < 64) {
        float mu = stats[tid] * invn;
        float var = stats[64 + tid] * invn - mu * mu;
        float rstd = rsqrtf(var + 1e-5f);
        float sc = rstd * gam[tid];
        sp[tid] = make_float2(sc, bet[tid] - mu * sc);
    }
    __syncthreads();
    int i = blockIdx.x * 256 + tid;
    if (i >= n32) return;
    int c2 = (i & 31) * 2;
    float2 p0 = sp[c2], p1 = sp[c2 + 1];
    float2 f = __half22float2(yin[i]);
    float vx = fmaxf(fmaf(f.x, p0.x, p0.y), 0.f);
    float vy = fmaxf(fmaf(f.y, p1.x, p1.y), 0.f);
    h16[i] = __float22half2_rn(make_float2(vx, vy));
}

// ---------------- 6/9: agg64s — MLP-16 fp16 gather-mean, fp16 out ----------------
__global__ void k_agg64s(const __half2* __restrict__ h,
                         __half2* __restrict__ aggout, float* __restrict__ zstats, int n) {
    if (blockIdx.x == 0 && threadIdx.x < 128 && zstats) zstats[threadIdx.x] = 0.f;
    int w = (blockIdx.x * blockDim.x + threadIdx.x) >> 5;
    int lane = threadIdx.x & 31;
    if (w >= n) return;
    int s = g_off[w], t = g_off[w + 1];
    float ax = 0.f, ay = 0.f;
    GATHER_MEAN(h, ax, ay, s, t, lane)
    float inv = 1.f / fmaxf((float)(t - s), 1.f);
    aggout[w * 32 + lane] = __float22half2_rn(make_float2(ax * inv, ay * inv));
}

// ---------------- 7/10: dense matmul via HMMA + BN-stats ----------------
__global__ void __launch_bounds__(256)
k_mm(const __half2* __restrict__ aggin, const __half2* __restrict__ hin,
     const float* __restrict__ Wl, const float* __restrict__ Wr,
     const float* __restrict__ bias, __half2* __restrict__ yout,
     float* __restrict__ stats, int n) {
    __shared__ unsigned int sW[64 * 65];
    __shared__ float sb[64];
    __shared__ float redS[8][64];
    __shared__ float redQ[8][64];
    int tid = threadIdx.x;
    for (int i = tid; i < 64 * 64; i += 256) {
        int kp = i >> 6, c = i & 63;
        int k0 = kp * 2, k1 = k0 + 1;
        float w0 = (k0 < 64) ? Wl[k0 * 64 + c] : Wr[(k0 - 64) * 64 + c];
        float w1 = (k1 < 64) ? Wl[k1 * 64 + c] : Wr[(k1 - 64) * 64 + c];
        __half2 hw = __floats2half2_rn(w0, w1);
        sW[kp * 65 + c] = *(unsigned int*)&hw;
    }
    if (tid < 64) sb[tid] = bias[tid];
    __syncthreads();

    int warp = tid >> 5, lane = tid & 31;
    int g = lane >> 2, tig = lane & 3;
    int nb = blockIdx.x * 128 + warp * 16;

    float acc[8][4];
#pragma unroll
    for (int nt = 0; nt < 8; nt++) {
        acc[nt][0] = 0.f; acc[nt][1] = 0.f; acc[nt][2] = 0.f; acc[nt][3] = 0.f;
    }

    int row0 = nb + g, row1 = nb + g + 8;
    bool v0 = row0 < n, v1 = row1 < n;
    int r0 = v0 ? row0 : n - 1;
    int r1 = v1 ? row1 : n - 1;

#pragma unroll
    for (int kt = 0; kt < 8; kt++) {
        const __half2* act = (kt < 4) ? aggin : hin;
        int kp = (kt & 3) * 8 + tig;
        unsigned int a0 = *(const unsigned int*)&act[r0 * 32 + kp];
        unsigned int a1 = *(const unsigned int*)&act[r1 * 32 + kp];
        unsigned int a2 = *(const unsigned int*)&act[r0 * 32 + kp + 4];
        unsigned int a3 = *(const unsigned int*)&act[r1 * 32 + kp + 4];
        int kb0 = (kt * 8 + tig) * 65;
        int kb1 = (kt * 8 + tig + 4) * 65;
#pragma unroll
        for (int nt = 0; nt < 8; nt++) {
            unsigned int b0 = sW[kb0 + nt * 8 + g];
            unsigned int b1 = sW[kb1 + nt * 8 + g];
            asm volatile(
                "mma.sync.aligned.m16n8k16.row.col.f32.f16.f16.f32 "
                "{%0,%1,%2,%3}, {%4,%5,%6,%7}, {%8,%9}, {%0,%1,%2,%3};"
                : "+f"(acc[nt][0]), "+f"(acc[nt][1]), "+f"(acc[nt][2]), "+f"(acc[nt][3])
                : "r"(a0), "r"(a1), "r"(a2), "r"(a3), "r"(b0), "r"(b1));
        }
    }

    float s0[8], s1[8], q0[8], q1[8];
#pragma unroll
    for (int nt = 0; nt < 8; nt++) {
        int c0 = nt * 8 + tig * 2;
        float y00 = acc[nt][0] + sb[c0];
        float y01 = acc[nt][1] + sb[c0 + 1];
        float y10 = acc[nt][2] + sb[c0];
        float y11 = acc[nt][3] + sb[c0 + 1];
        if (v0) yout[row0 * 32 + nt * 4 + tig] = __float22half2_rn(make_float2(y00, y01));
        if (v1) yout[row1 * 32 + nt * 4 + tig] = __float22half2_rn(make_float2(y10, y11));
        s0[nt] = (v0 ? y00 : 0.f) + (v1 ? y10 : 0.f);
        s1[nt] = (v0 ? y01 : 0.f) + (v1 ? y11 : 0.f);
        q0[nt] = (v0 ? y00 * y00 : 0.f) + (v1 ? y10 * y10 : 0.f);
        q1[nt] = (v0 ? y01 * y01 : 0.f) + (v1 ? y11 * y11 : 0.f);
    }
#pragma unroll
    for (int d = 4; d <= 16; d <<= 1) {
#pragma unroll
        for (int nt = 0; nt < 8; nt++) {
            s0[nt] += __shfl_xor_sync(0xffffffffu, s0[nt], d);
            s1[nt] += __shfl_xor_sync(0xffffffffu, s1[nt], d);
            q0[nt] += __shfl_xor_sync(0xffffffffu, q0[nt], d);
            q1[nt] += __shfl_xor_sync(0xffffffffu, q1[nt], d);
        }
    }
    if (g == 0) {
#pragma unroll
        for (int nt = 0; nt < 8; nt++) {
            int c0 = nt * 8 + tig * 2;
            redS[warp][c0] = s0[nt]; redS[warp][c0 + 1] = s1[nt];
            redQ[warp][c0] = q0[nt]; redQ[warp][c0 + 1] = q1[nt];
        }
    }
    __syncthreads();
    if (tid < 64) {
        float s = 0.f, q = 0.f;
#pragma unroll
        for (int w2 = 0; w2 < 8; w2++) { s += redS[w2][tid]; q += redQ[w2][tid]; }
        atomicAdd(&stats[tid], s);
        atomicAdd(&stats[64 + tid], q);
    }
}

// ---------------- 11: pooling (BN3 + ReLU on read) ----------------
__global__ void k_pool(const void* __restrict__ batch, const void* __restrict__ ei,
                       const float* __restrict__ x,
                       const __half2* __restrict__ y16,
                       const float* __restrict__ stats,
                       const float* __restrict__ gam, const float* __restrict__ bet,
                       float invn, int n) {
    __shared__ float w[64];
    __shared__ int bb[64];
    __shared__ float2 sscsh[64];
    __shared__ int s_is64;
    int is64 = block_is64((const long long*)ei, n, &s_is64);
    int tid = threadIdx.x;  // 0..31
    int base = blockIdx.x * 64;
    float S = g_sumexp;
    for (int j = tid; j < 64; j += 32) {
        int i = base + j;
        if (i < n) { w[j] = expf(__ldg(&x[i * 6 + 4])) / S; bb[j] = load_idx2(batch, i, is64); }
        else { w[j] = 0.f; bb[j] = -1; }
        float mu = stats[j] * invn;
        float var = stats[64 + j] * invn - mu * mu;
        float rstd = rsqrtf(var + 1e-5f);
        float sc = rstd * gam[j];
        sscsh[j] = make_float2(sc, bet[j] - mu * sc);
    }
    __syncthreads();
    int c0 = tid * 2;
    float2 p0 = sscsh[c0], p1 = sscsh[c0 + 1];
    int m = n - base; if (m > 64) m = 64;
#define BNV(f) make_float2(fmaxf(fmaf((f).x, p0.x, p0.y), 0.f), fmaxf(fmaf((f).y, p1.x, p1.y), 0.f))
    if (m == 64 && bb[0] == bb[63]) {
        float ax0 = 0.f, ay0 = 0.f, ax1 = 0.f, ay1 = 0.f;
        float ax2 = 0.f, ay2 = 0.f, ax3 = 0.f, ay3 = 0.f;
        for (int j = 0; j < 64; j += 4) {
            float2 f0 = BNV(__half22float2(__ldg(&y16[(base + j + 0) * 32 + tid])));
            float2 f1 = BNV(__half22float2(__ldg(&y16[(base + j + 1) * 32 + tid])));
            float2 f2 = BNV(__half22float2(__ldg(&y16[(base + j + 2) * 32 + tid])));
            float2 f3 = BNV(__half22float2(__ldg(&y16[(base + j + 3) * 32 + tid])));
            ax0 += w[j] * f0.x;     ay0 += w[j] * f0.y;
            ax1 += w[j + 1] * f1.x; ay1 += w[j + 1] * f1.y;
            ax2 += w[j + 2] * f2.x; ay2 += w[j + 2] * f2.y;
            ax3 += w[j + 3] * f3.x; ay3 += w[j + 3] * f3.y;
        }
        atomicAdd(&g_pool[bb[0] * 64 + c0],     (ax0 + ax1) + (ax2 + ax3));
        atomicAdd(&g_pool[bb[0] * 64 + c0 + 1], (ay0 + ay1) + (ay2 + ay3));
    } else {
        float accx = 0.f, accy = 0.f;
        int cur = bb[0];
        for (int j = 0; j < m; j++) {
            int b = bb[j];
            if (b != cur) {
                if (cur >= 0) {
                    atomicAdd(&g_pool[cur * 64 + c0], accx);
                    atomicAdd(&g_pool[cur * 64 + c0 + 1], accy);
                }
                accx = 0.f; accy = 0.f; cur = b;
            }
            float2 f = BNV(__half22float2(__ldg(&y16[(base + j) * 32 + tid])));
            accx += w[j] * f.x; accy += w[j] * f.y;
        }
        if (cur >= 0 && m > 0) {
            atomicAdd(&g_pool[cur * 64 + c0], accx);
            atomicAdd(&g_pool[cur * 64 + c0 + 1], accy);
        }
    }
#undef BNV
}

// ---------------- 12: heads (+ restore zeros) ----------------
__global__ void k_head(const float* __restrict__ phW1, const float* __restrict__ phb1,
                       const float* __restrict__ phW2, const float* __restrict__ phb2,
                       const float* __restrict__ trW1, const float* __restrict__ trb1,
                       const float* __restrict__ trW2, const float* __restrict__ trb2,
                       float* __restrict__ zstats, float* __restrict__ out) {
    __shared__ float pool[64 * 64];
    __shared__ float hid[64 * 32];
    __shared__ float hidt[64 * 16];
    int tid = threadIdx.x;
    for (int i = tid; i < 64 * 64; i += 256) {
        int b = i >> 6;
        float c = (float)g_bcnt[b];
        pool[i] = g_pool[i] / fmaxf(c, 1.f);
    }
    __syncthreads();
    for (int i = tid; i < 64 * 64; i += 256) g_pool[i] = 0.f;
    if (tid < 64) g_bcnt[tid] = 0;
    if (tid < 128) zstats[tid] = 0.f;
    if (tid == 0) g_sumexp = 0.f;

    for (int i = tid; i < 64 * 32; i += 256) {
        int b = i >> 5, j = i & 31;
        float s = phb1[j];
        for (int k = 0; k < 64; k++) s += pool[b * 64 + k] * phW1[k * 32 + j];
        hid[i] = fmaxf(s, 0.f);
    }
    for (int i = tid; i < 64 * 16; i += 256) {
        int b = i >> 4, j = i & 15;
        float s = trb1[j];
        for (int k = 0; k < 64; k++) s += pool[b * 64 + k] * trW1[k * 16 + j];
        hidt[i] = fmaxf(s, 0.f);
    }
    __syncthreads();
    for (int i = tid; i < 64 * 3; i += 256) {
        int b = i / 3, j = i - b * 3;
        float s = phb2[j];
        for (int k = 0; k < 32; k++) s += hid[b * 32 + k] * phW2[k * 3 + j];
        out[i] = s;
    }
    for (int i = tid; i < 64; i += 256) {
        float s = trb2[0];
        for (int k = 0; k < 16; k++) s += hidt[i * 16 + k] * trW2[k];
        out[192 + i] = 1.f / (1.f + expf(-s));
    }
}

// ---------------- launch ----------------
extern "C" void kernel_launch(void* const* d_in, const int* in_sizes, int n_in,
                              void* d_out, int out_size) {
    const float* x   = (const float*)d_in[0];
    const void*  ei  = d_in[1];
    const void*  bat = d_in[2];
    const float* W1l = (const float*)d_in[3];
    const float* b1  = (const float*)d_in[4];
    const float* W1r = (const float*)d_in[5];
    const float* W2l = (const float*)d_in[6];
    const float* b2  = (const float*)d_in[7];
    const float* W2r = (const float*)d_in[8];
    const float* W3l = (const float*)d_in[9];
    const float* b3  = (const float*)d_in[10];
    const float* W3r = (const float*)d_in[11];
    const float* g1  = (const float*)d_in[12];
    const float* be1 = (const float*)d_in[13];
    const float* g2  = (const float*)d_in[14];
    const float* be2 = (const float*)d_in[15];
    const float* g3  = (const float*)d_in[16];
    const float* be3 = (const float*)d_in[17];
    const float* phW1 = (const float*)d_in[18];
    const float* phb1 = (const float*)d_in[19];
    const float* phW2 = (const float*)d_in[20];
    const float* phb2 = (const float*)d_in[21];
    const float* trW1 = (const float*)d_in[22];
    const float* trb1 = (const float*)d_in[23];
    const float* trW2 = (const float*)d_in[24];
    const float* trb2 = (const float*)d_in[25];
    float* out = (float*)d_out;

    int n = in_sizes[0] / 6;
    int e = in_sizes[1] / 2;

    float *p_v32, *p_stats;
    __half2 *p_ya, *p_yb, *p_h16, *p_agg16;
    cudaGetSymbolAddress((void**)&p_v32, g_v32);
    cudaGetSymbolAddress((void**)&p_stats, g_stats);
    cudaGetSymbolAddress((void**)&p_ya, g_y16a);
    cudaGetSymbolAddress((void**)&p_yb, g_y16b);
    cudaGetSymbolAddress((void**)&p_h16, g_h16);
    cudaGetSymbolAddress((void**)&p_agg16, g_agg16);

    int nb = (n + 1023) / 1024;
    int eBlocks = (e + 255) / 256;
    int aggBlocks = (n * 32 + 255) / 256;   // warp-per-node grids
    int mmBlocks = (n + 63) / 64;           // warp-per-8-nodes grids
    int mmaBlocks = (n + 127) / 128;        // HMMA: 128 nodes per block
    int bnBlocks = (n * 32 + 255) / 256;
    float invn = 1.f / (float)n;

    // 1-3: CSR (+ l1pre fused into scanA)
    k_hist<<<eBlocks, 256>>>(ei, x, bat, e, n);
    k_scanA<<<nb, 1024>>>(x, W1l, W1r, b1, p_h16, (float2*)p_v32, n);
    k_scatter<<<eBlocks, 256>>>(ei, e, n, nb);

    // 4: layer 1 gather (linearity)
    k_l1agg<<<mmBlocks, 256>>>(p_h16, (const float2*)p_v32, p_ya, p_stats + 0 * 128, n);

    // 5-7: layer 2 (fp16 datapath, HMMA matmul)
    k_bnh<<<bnBlocks, 256>>>(p_ya, p_stats + 0 * 128, g1, be1, invn, p_h16, n * 32);
    k_agg64s<<<aggBlocks, 256>>>(p_h16, p_agg16, p_stats + 0 * 128, n);
    k_mm<<<mmaBlocks, 256>>>(p_agg16, p_h16, W2l, W2r, b2, p_yb, p_stats + 1 * 128, n);

    // 8-10: layer 3
    k_bnh<<<bnBlocks, 256>>>(p_yb, p_stats + 1 * 128, g2, be2, invn, p_h16, n * 32);
    k_agg64s<<<aggBlocks, 256>>>(p_h16, p_agg16, p_stats + 1 * 128, n);
    k_mm<<<mmaBlocks, 256>>>(p_agg16, p_h16, W3l, W3r, b3, p_ya, p_stats + 2 * 128, n);

    // 11-12: pooling + heads
    k_pool<<<mmBlocks, 32>>>(bat, ei, x, p_ya, p_stats + 2 * 128, g3, be3, invn, n);
    k_head<<<1, 256>>>(phW1, phb1, phW2, phb2, trW1, trb1, trW2, trb2, p_stats + 2 * 128, out);
}